// round 1
// baseline (speedup 1.0000x reference)
#include <cuda_runtime.h>
#include <cstdint>
#include <cstddef>

// Router: top-1 MoE routing with capacity constraint.
// Outputs (concatenated float32): dispatch[N,8,Ccap], combine[N,8,Ccap], z, aux, div, std
//
// Pipeline (all on default stream, graph-capturable):
//   1) cudaMemsetAsync(d_out, 0)                      -- 805MB zero fill (the roofline)
//   2) init_acc                                       -- zero 55 accumulators
//   3) token_kernel: softmax/argmax + warp-reduced partial sums
//   4) rank_kernel:  stable rank per token (brute force, shared broadcast) + scatter
//   5) scalar_kernel: finalize 4 scalars

#define E 8
#define MAXN 8192
#define NACC 55   // 0:z  1..8:psum  9..16:cnt  17..52:G(upper tri 36)  53:sum  54:sumsq

__device__ float g_prob[MAXN];
__device__ int   g_expert[MAXN];
__device__ float g_acc[NACC];

__global__ void init_acc_kernel() {
    int t = threadIdx.x;
    if (t < NACC) g_acc[t] = 0.0f;
}

__global__ void token_kernel(const float* __restrict__ logits, int N) {
    int i = blockIdx.x * blockDim.x + threadIdx.x;
    float vals[NACC];
#pragma unroll
    for (int k = 0; k < NACC; k++) vals[k] = 0.0f;

    if (i < N) {
        // load raw logits (8 contiguous floats)
        float4 r0 = reinterpret_cast<const float4*>(logits)[2 * i + 0];
        float4 r1 = reinterpret_cast<const float4*>(logits)[2 * i + 1];
        float raw[E] = {r0.x, r0.y, r0.z, r0.w, r1.x, r1.y, r1.z, r1.w};

        float l[E];
        float s = 0.f, s2 = 0.f;
#pragma unroll
        for (int j = 0; j < E; j++) {
            s  += raw[j];
            s2 += raw[j] * raw[j];
            float c = fminf(fmaxf(raw[j], -10.0f), 10.0f);
            l[j] = c / 1.5f;                 // IEEE div, matches JAX clip/temp
        }
        vals[53] = s;
        vals[54] = s2;

        // argmax (first max) + max
        float m = l[0]; int e = 0;
#pragma unroll
        for (int j = 1; j < E; j++) {
            if (l[j] > m) { m = l[j]; e = j; }
        }

        // softmax denominator, per-expert prob sums
        float sumexp = 0.f;
        float ex[E];
#pragma unroll
        for (int j = 0; j < E; j++) { ex[j] = expf(l[j] - m); sumexp += ex[j]; }
#pragma unroll
        for (int j = 0; j < E; j++) vals[1 + j] = ex[j] / sumexp;

        // expert_prob exactly as JAX: exp(0)/sumexp = 1/sumexp
        float p = 1.0f / sumexp;
        g_prob[i]   = p;
        g_expert[i] = e;

        vals[9 + e] = 1.0f;  // count one-hot

        // z loss partial
        float lse = m + logf(sumexp);
        vals[0] = lse * lse;

        // Gram matrix partials (upper tri incl diag, 36)
        int t = 0;
#pragma unroll
        for (int a = 0; a < E; a++)
#pragma unroll
            for (int b = a; b < E; b++) vals[17 + t++] = l[a] * l[b];
    }

    // warp reduce then atomicAdd
    int lane = threadIdx.x & 31;
#pragma unroll
    for (int k = 0; k < NACC; k++) {
        float v = vals[k];
        v += __shfl_down_sync(0xffffffffu, v, 16);
        v += __shfl_down_sync(0xffffffffu, v, 8);
        v += __shfl_down_sync(0xffffffffu, v, 4);
        v += __shfl_down_sync(0xffffffffu, v, 2);
        v += __shfl_down_sync(0xffffffffu, v, 1);
        if (lane == 0) atomicAdd(&g_acc[k], v);
    }
}

// One thread per token. Stable rank = #{j : e_j==e_i && (p_j>p_i || (p_j==p_i && j<i))}.
// This equals JAX: argsort(-p) (stable) -> per-expert cumsum position.
__global__ void rank_scatter_kernel(float* __restrict__ dispatch_out,
                                    float* __restrict__ combine_out,
                                    int N, int Ccap) {
    __shared__ float   sp[MAXN];
    __shared__ uint8_t se[MAXN];

    for (int k = threadIdx.x; k < N; k += blockDim.x) {
        sp[k] = g_prob[k];
        se[k] = (uint8_t)g_expert[k];
    }
    __syncthreads();

    int i = blockIdx.x * blockDim.x + threadIdx.x;
    if (i >= N) return;

    float pi = sp[i];
    int   ei = se[i];
    int rank = 0;

    const float4* sp4 = reinterpret_cast<const float4*>(sp);
    const uchar4* se4 = reinterpret_cast<const uchar4*>(se);
    int n4 = N >> 2;
#pragma unroll 4
    for (int j4 = 0; j4 < n4; ++j4) {
        float4 p4 = sp4[j4];       // broadcast across warp (lockstep j4)
        uchar4 e4 = se4[j4];
        int j = j4 << 2;
        rank += (e4.x == ei) && ((p4.x > pi) || (p4.x == pi && (j + 0) < i));
        rank += (e4.y == ei) && ((p4.y > pi) || (p4.y == pi && (j + 1) < i));
        rank += (e4.z == ei) && ((p4.z > pi) || (p4.z == pi && (j + 2) < i));
        rank += (e4.w == ei) && ((p4.w > pi) || (p4.w == pi && (j + 3) < i));
    }

    if (rank < Ccap) {
        size_t base = ((size_t)i * E + ei) * (size_t)Ccap + (size_t)rank;
        dispatch_out[base] = 1.0f;
        combine_out[base]  = pi;
    }
}

__global__ void scalar_kernel(float* __restrict__ out_scalars, int N) {
    if (threadIdx.x != 0 || blockIdx.x != 0) return;

    float z_loss = g_acc[0] / (float)N;

    float aux = 0.f;
    for (int e = 0; e < E; e++) aux += g_acc[9 + e] * g_acc[1 + e];
    aux = aux * (float)E / ((float)N * (float)N);

    // Gram upper-tri -> correlation off-diag squared sum
    float G[E][E];
    int t = 0;
    for (int a = 0; a < E; a++)
        for (int b = a; b < E; b++) { G[a][b] = g_acc[17 + t]; G[b][a] = g_acc[17 + t]; t++; }
    float nrm[E];
    for (int a = 0; a < E; a++) nrm[a] = fmaxf(sqrtf(G[a][a]), 1e-12f);
    float div = 0.f;
    for (int a = 0; a < E; a++)
        for (int b = a + 1; b < E; b++) {
            float c = G[a][b] / (nrm[a] * nrm[b]);
            div += 2.0f * c * c;
        }
    div /= (float)(E * (E - 1));

    double M = (double)N * E;
    double sm = (double)g_acc[53], sq = (double)g_acc[54];
    double var = (sq - sm * sm / M) / (M - 1.0);
    float stdv = (float)sqrt(var);

    out_scalars[0] = z_loss;
    out_scalars[1] = aux;
    out_scalars[2] = div;
    out_scalars[3] = stdv;
}

extern "C" void kernel_launch(void* const* d_in, const int* in_sizes, int n_in,
                              void* d_out, int out_size) {
    const float* logits = (const float*)d_in[1];
    int N = in_sizes[1] / E;                 // 8192
    int Ccap = (int)((3 * N + 2 * E - 1) / (2 * E));  // ceil(1.5*N/E)
    if (Ccap < 1) Ccap = 1;

    float* out = (float*)d_out;
    size_t D = (size_t)N * E * (size_t)Ccap;
    float* dispatch_out = out;
    float* combine_out  = out + D;
    float* scalars_out  = out + 2 * D;

    // 1) zero the whole output (dominant cost; one HBM-bound memset node)
    cudaMemsetAsync(d_out, 0, (size_t)out_size * sizeof(float));

    // 2) accumulators
    init_acc_kernel<<<1, 64>>>();

    // 3) per-token softmax/argmax + reductions
    token_kernel<<<(N + 255) / 256, 256>>>(logits, N);

    // 4) stable rank + scatter
    rank_scatter_kernel<<<(N + 255) / 256, 256>>>(dispatch_out, combine_out, N, Ccap);

    // 5) scalars
    scalar_kernel<<<1, 32>>>(scalars_out, N);
}